// round 15
// baseline (speedup 1.0000x reference)
#include <cuda_runtime.h>
#include <cuda_fp16.h>
#include <math.h>
#include <stdint.h>

// ---------------------------------------------------------------------------
// MTCNN P-Net forward. Full fp16 tensor-core pipeline.
// conv1: mma.sync implicit GEMM (M=16 conv-x, N=16co pad, K=32 pad) + fused
//        maxpool via shfl (prelu after max; bias/norm folded), fp16 staged smem.
// conv2/conv3: mma.sync fp16 ROW-STREAMING (unchanged from R14).
// conv3 fuses 1x1 heads + softmax.
// ---------------------------------------------------------------------------

#define B       16
#define H0      720
#define HP      359
#define H2      357
#define H3      355
#define P3      (H3*H3)

// activations: per pixel 8 uint32 = 8 ch-pairs fp16x2 (32B/pixel)
__device__ uint32_t g_p1h[(size_t)B*HP*HP*8];
__device__ uint32_t g_c2h[(size_t)B*H2*H2*8];

// ======================= mma.sync helpers (fp16) ===========================
__device__ __forceinline__ void mma16816h(float* d, const uint32_t* a,
                                          uint32_t b0, uint32_t b1) {
    asm volatile(
        "mma.sync.aligned.m16n8k16.row.col.f32.f16.f16.f32 "
        "{%0,%1,%2,%3}, {%4,%5,%6,%7}, {%8,%9}, {%0,%1,%2,%3};"
        : "+f"(d[0]), "+f"(d[1]), "+f"(d[2]), "+f"(d[3])
        : "r"(a[0]), "r"(a[1]), "r"(a[2]), "r"(a[3]), "r"(b0), "r"(b1));
}
__device__ __forceinline__ uint32_t packh(__half a, __half b) {
    __half2 t = __halves2half2(a, b);
    return *(uint32_t*)&t;
}

// load one input-row batch: 12 uint32 frag regs (kx 0..2 x {p0,p1} x {q4,q4+4})
__device__ __forceinline__ void load_ky1(uint32_t (&L)[12], const uint32_t* rp,
                                         int p0c, int p1c, int q4) {
    #pragma unroll
    for (int kx = 0; kx < 3; kx++) {
        L[kx*4+0] = rp[(p0c + kx)*8 + q4];
        L[kx*4+1] = rp[(p1c + kx)*8 + q4];
        L[kx*4+2] = rp[(p0c + kx)*8 + q4 + 4];
        L[kx*4+3] = rp[(p1c + kx)*8 + q4 + 4];
    }
}

// ---------------------------------------------------------------------------
// Kernel 1: conv1(3x3,3->10)+PReLU+maxpool2 via mma.sync, out fp16 ch-last.
// Block 256 thr = 8 warps; each warp: 16 conv-x x 2 conv rows -> 8 pooled px.
// Block covers 64 pooled px (x) x 1 pooled row. K=32: k=ci*9+ky*3+kx, pad->0
// via zeroed ci=3 smem plane. Norm (x-127.5)*s folded into weights/bias.
// ---------------------------------------------------------------------------
__global__ __launch_bounds__(256) void k_conv1_mma(
    const float* __restrict__ x, const float* __restrict__ w1,
    const float* __restrict__ b1, const float* __restrict__ a1)
{
    __shared__ __align__(16) __half sIn[4*4*132];  // [ci 0..3][row 0..3][x 0..131]
    __shared__ uint2 sWf[2*2*32];                  // [kc][ng][lane]
    __shared__ float sBA[32];                      // bias[16], alpha[16]

    const int b   = blockIdx.z;
    const int py  = blockIdx.y;
    const int bx  = blockIdx.x;
    const int tid = threadIdx.x;
    const int wid = tid >> 5, lane = tid & 31;
    const int tg  = lane & 3, g = lane >> 2;
    const float SC = 0.0078125f;

    // ---- weight fragments (norm-scaled, padded)
    if (tid < 128) {
        int kc = tid >> 6, ng = (tid >> 5) & 1, ln = tid & 31;
        int tg_ = ln & 3, g_ = ln >> 2;
        int co = ng*8 + g_;
        int kb = kc*16 + 2*tg_;
        float v0=0.f, v1=0.f, v2=0.f, v3=0.f;
        if (co < 10) {
            if (kb   < 27) v0 = w1[co*27 + kb  ] * SC;
            if (kb+1 < 27) v1 = w1[co*27 + kb+1] * SC;
            if (kb+8 < 27) v2 = w1[co*27 + kb+8] * SC;
            if (kb+9 < 27) v3 = w1[co*27 + kb+9] * SC;
        }
        __half2 h0 = __floats2half2_rn(v0, v1);
        __half2 h1 = __floats2half2_rn(v2, v3);
        sWf[tid] = make_uint2(*(uint32_t*)&h0, *(uint32_t*)&h1);
    }
    if (tid < 16) {
        float bb = 0.f, aa = 1.f;
        if (tid < 10) {
            float s = 0.f;
            #pragma unroll
            for (int k = 0; k < 27; k++) s += w1[tid*27 + k];
            bb = b1[tid] - 127.5f * SC * s;
            aa = a1[tid];
        }
        sBA[tid] = bb; sBA[16+tid] = aa;
    }
    // zero plane ci=3 (528 halves = 264 u32), absorbs padded k>=27
    for (int i = tid; i < 264; i += 256)
        ((uint32_t*)(sIn + 3*528))[i] = 0;

    // ---- stage input: rows 2py..2py+3, x in [128bx, 128bx+130), 3 ci (raw x)
    {
        const int gx0 = 128*bx;
        const int gy0 = 2*py;
        for (int e = tid; e < 1560; e += 256) {
            int ci  = e / 520;
            int rem = e - ci*520;
            int r   = rem / 130;
            int lx  = rem - r*130;
            int gx  = gx0 + lx;
            float v = (gx < H0) ? x[((b*3+ci)*H0 + gy0 + r)*H0 + gx] : 0.f;
            sIn[(ci*4 + r)*132 + lx] = __float2half_rn(v);
        }
    }
    __syncthreads();

    // ---- per-lane k-offsets (8 k values: {0,1,8,9,16,17,24,25} + 2tg)
    int koff[8];
    #pragma unroll
    for (int j = 0; j < 8; j++) {
        int k = (j >> 1)*8 + (j & 1) + 2*tg;
        int ci = k / 9, t = k - ci*9, ky = t / 3, kx = t - ky*3;
        if (k >= 27) { ci = 3; ky = 0; kx = 0; }
        koff[j] = ci*528 + ky*132 + kx;
    }

    const int xw = wid * 16;          // local x of M-row 0

    float acc[2][2][4];               // [conv row ty][ng][4]
    #pragma unroll
    for (int ty = 0; ty < 2; ty++)
        #pragma unroll
        for (int ng = 0; ng < 2; ng++)
            #pragma unroll
            for (int j = 0; j < 4; j++) acc[ty][ng][j] = 0.f;

    #pragma unroll
    for (int ty = 0; ty < 2; ty++) {
        const int base0 = ty*132 + xw + g;
        const int base1 = base0 + 8;
        #pragma unroll
        for (int kc = 0; kc < 2; kc++) {
            const int j0 = kc*4;
            uint32_t A[4];
            A[0] = packh(sIn[koff[j0  ]+base0], sIn[koff[j0+1]+base0]);
            A[1] = packh(sIn[koff[j0  ]+base1], sIn[koff[j0+1]+base1]);
            A[2] = packh(sIn[koff[j0+2]+base0], sIn[koff[j0+3]+base0]);
            A[3] = packh(sIn[koff[j0+2]+base1], sIn[koff[j0+3]+base1]);
            #pragma unroll
            for (int ng = 0; ng < 2; ng++) {
                uint2 f = sWf[(kc*2 + ng)*32 + lane];
                mma16816h(acc[ty][ng], A, f.x, f.y);
            }
        }
    }

    // ---- pooling epilogue: max over ty (in-lane), then over x-pair (shfl^4),
    // then bias + prelu, pack, store.
    const int pxb = 64*bx + 8*wid;
    #pragma unroll
    for (int ng = 0; ng < 2; ng++) {
        float m0 = fmaxf(acc[0][ng][0], acc[1][ng][0]);  // row g,   co 8ng+2tg
        float m1 = fmaxf(acc[0][ng][1], acc[1][ng][1]);  // row g,   co +1
        float m2 = fmaxf(acc[0][ng][2], acc[1][ng][2]);  // row g+8, co 8ng+2tg
        float m3 = fmaxf(acc[0][ng][3], acc[1][ng][3]);  // row g+8, co +1
        m0 = fmaxf(m0, __shfl_xor_sync(0xffffffffu, m0, 4));
        m1 = fmaxf(m1, __shfl_xor_sync(0xffffffffu, m1, 4));
        m2 = fmaxf(m2, __shfl_xor_sync(0xffffffffu, m2, 4));
        m3 = fmaxf(m3, __shfl_xor_sync(0xffffffffu, m3, 4));

        if ((g & 1) == 0) {
            const int co = 8*ng + 2*tg;
            const float b0 = sBA[co], b1v = sBA[co+1];
            const float a0 = sBA[16+co], a1v = sBA[16+co+1];
            float v0 = m0 + b0; v0 = (v0 >= 0.f) ? v0 : a0*v0;
            float v1 = m1 + b1v; v1 = (v1 >= 0.f) ? v1 : a1v*v1;
            float v2 = m2 + b0; v2 = (v2 >= 0.f) ? v2 : a0*v2;
            float v3 = m3 + b1v; v3 = (v3 >= 0.f) ? v3 : a1v*v3;
            __half2 lo = __floats2half2_rn(v0, v1);
            __half2 hi = __floats2half2_rn(v2, v3);
            const int ppx_lo = pxb + (g >> 1);
            const int ppx_hi = ppx_lo + 4;
            const size_t rowb = (size_t)(b*HP + py) * HP;
            const int ui = ng*4 + tg;
            if (ppx_lo < HP) g_p1h[(rowb + ppx_lo)*8 + ui] = *(uint32_t*)&lo;
            if (ppx_hi < HP) g_p1h[(rowb + ppx_hi)*8 + ui] = *(uint32_t*)&hi;
        }
    }
}

// ---------------------------------------------------------------------------
// Kernel 2: conv2 via mma.sync fp16, ROW-STREAMING (4 rows, 6 input rows).
// ---------------------------------------------------------------------------
__global__ __launch_bounds__(256, 2) void k_conv2_mma(
    const float* __restrict__ w, const float* __restrict__ bias,
    const float* __restrict__ alpha)
{
    __shared__ uint2 sWf[9*2*32];
    __shared__ float sBA[32];

    const int b    = blockIdx.z;
    const int ox0  = blockIdx.x * 128;
    const int oy0  = blockIdx.y * 4;
    const int tid  = threadIdx.x;
    const int wid  = tid >> 5;
    const int lane = tid & 31;

    for (int f = tid; f < 9*2*32; f += 256) {
        int kc = f >> 6, cg = (f >> 5) & 1, ln = f & 31;
        int g = ln >> 2, ci0 = (ln & 3) * 2;
        int co = cg*8 + g;
        int ky = kc / 3, kx = kc % 3;
        float w0 = (ci0   < 10) ? w[((co*10 + ci0  )*3 + ky)*3 + kx] : 0.f;
        float w1v= (ci0+1 < 10) ? w[((co*10 + ci0+1)*3 + ky)*3 + kx] : 0.f;
        float w2 = (ci0+8 < 10) ? w[((co*10 + ci0+8)*3 + ky)*3 + kx] : 0.f;
        float w3 = (ci0+9 < 10) ? w[((co*10 + ci0+9)*3 + ky)*3 + kx] : 0.f;
        __half2 b0 = __floats2half2_rn(w0, w1v);
        __half2 b1 = __floats2half2_rn(w2, w3);
        sWf[f] = make_uint2(*(uint32_t*)&b0, *(uint32_t*)&b1);
    }
    if (tid < 16) { sBA[tid] = bias[tid]; sBA[16+tid] = alpha[tid]; }
    __syncthreads();

    const int q4  = lane & 3;
    const int g   = lane >> 2;
    const int ci0 = q4 * 2;

    const int p0  = ox0 + wid * 16 + g;
    const int p1  = p0 + 8;
    const int p0c = min(p0, H2 - 1);
    const int p1c = min(p1, H2 - 1);

    float acc[4][2][4];
    #pragma unroll
    for (int r = 0; r < 4; r++)
        #pragma unroll
        for (int cg = 0; cg < 2; cg++)
            #pragma unroll
            for (int j = 0; j < 4; j++) acc[r][cg][j] = 0.f;

    uint32_t cur[12], nxt[12];
    load_ky1(cur, &g_p1h[(size_t)(b*HP + min(oy0, HP-1)) * HP * 8], p0c, p1c, q4);

    #pragma unroll
    for (int i = 0; i < 6; i++) {
        if (i < 5)
            load_ky1(nxt, &g_p1h[(size_t)(b*HP + min(oy0+i+1, HP-1)) * HP * 8],
                     p0c, p1c, q4);
        #pragma unroll
        for (int kx = 0; kx < 3; kx++) {
            uint32_t ah[4] = {cur[kx*4+0], cur[kx*4+1], cur[kx*4+2], cur[kx*4+3]};
            #pragma unroll
            for (int r = 0; r < 4; r++) {
                if (r > i || r < i - 2) continue;
                const int kc = 3*(i - r) + kx;
                uint2 f0 = sWf[(kc*2 + 0)*32 + lane];
                uint2 f1 = sWf[(kc*2 + 1)*32 + lane];
                mma16816h(acc[r][0], ah, f0.x, f0.y);
                mma16816h(acc[r][1], ah, f1.x, f1.y);
            }
        }
        #pragma unroll
        for (int j = 0; j < 12; j++) cur[j] = nxt[j];
    }

    #pragma unroll
    for (int r = 0; r < 4; r++) {
        const int oy = oy0 + r;
        if (oy >= H2) break;
        const size_t rowbase = (size_t)(b*H2 + oy) * H2;
        #pragma unroll
        for (int cg = 0; cg < 2; cg++) {
            const int co = cg*8 + ci0;
            const float b0 = sBA[co], b1 = sBA[co+1];
            const float a0 = sBA[16+co], a1 = sBA[16+co+1];
            float t0 = acc[r][cg][0] + b0, t1 = acc[r][cg][1] + b1;
            float t2 = acc[r][cg][2] + b0, t3 = acc[r][cg][3] + b1;
            float o00 = (t0 >= 0.f) ? t0 : a0*t0;
            float o01 = (t1 >= 0.f) ? t1 : a1*t1;
            float o10 = (t2 >= 0.f) ? t2 : a0*t2;
            float o11 = (t3 >= 0.f) ? t3 : a1*t3;
            __half2 s0 = __floats2half2_rn(o00, o01);
            __half2 s1 = __floats2half2_rn(o10, o11);
            if (p0 < H2) g_c2h[(rowbase + p0)*8 + cg*4 + q4] = *(uint32_t*)&s0;
            if (p1 < H2) g_c2h[(rowbase + p1)*8 + cg*4 + q4] = *(uint32_t*)&s1;
        }
    }
}

// ---------------------------------------------------------------------------
// Kernel 3: conv3 ROW-STREAMING + fused heads + softmax.
// ---------------------------------------------------------------------------
__global__ __launch_bounds__(256, 2) void k_conv3_heads(
    const float* __restrict__ w, const float* __restrict__ bias,
    const float* __restrict__ alpha,
    const float* __restrict__ w41, const float* __restrict__ b41,
    const float* __restrict__ w42, const float* __restrict__ b42,
    float* __restrict__ out)
{
    __shared__ uint2 sWf[9*4*32];
    __shared__ float sBA[64];
    __shared__ float sHW[6][32];
    __shared__ float sHB[6];

    const int b    = blockIdx.z;
    const int ox0  = blockIdx.x * 128;
    const int oy0  = blockIdx.y * 4;
    const int tid  = threadIdx.x;
    const int wid  = tid >> 5;
    const int lane = tid & 31;

    for (int f = tid; f < 9*4*32; f += 256) {
        int kc = f >> 7, cg = (f >> 5) & 3, ln = f & 31;
        int g = ln >> 2, ci0 = (ln & 3) * 2;
        int co = cg*8 + g;
        int ky = kc / 3, kx = kc % 3;
        __half2 b0 = __floats2half2_rn(w[((co*16 + ci0  )*3 + ky)*3 + kx],
                                       w[((co*16 + ci0+1)*3 + ky)*3 + kx]);
        __half2 b1 = __floats2half2_rn(w[((co*16 + ci0+8)*3 + ky)*3 + kx],
                                       w[((co*16 + ci0+9)*3 + ky)*3 + kx]);
        sWf[f] = make_uint2(*(uint32_t*)&b0, *(uint32_t*)&b1);
    }
    if (tid < 32) { sBA[tid] = bias[tid]; sBA[32+tid] = alpha[tid]; }
    if (tid < 64)  sHW[tid/32][tid%32] = w41[tid];
    if (tid >= 64 && tid < 192) sHW[2 + (tid-64)/32][(tid-64)%32] = w42[tid-64];
    if (tid < 2) sHB[tid] = b41[tid];
    if (tid >= 2 && tid < 6) sHB[tid] = b42[tid-2];
    __syncthreads();

    const int q4  = lane & 3;
    const int g   = lane >> 2;
    const int ci0 = q4 * 2;
    const int q   = q4;

    const int p0  = ox0 + wid * 16 + g;
    const int p1  = p0 + 8;
    const int p0c = min(p0, H3 - 1);
    const int p1c = min(p1, H3 - 1);

    float* regp  = out;
    float* probp = out + (size_t)B * 4 * P3;

    float acc[4][4][4];
    #pragma unroll
    for (int r = 0; r < 4; r++)
        #pragma unroll
        for (int cg = 0; cg < 4; cg++)
            #pragma unroll
            for (int j = 0; j < 4; j++) acc[r][cg][j] = 0.f;

    uint32_t cur[12], nxt[12];
    load_ky1(cur, &g_c2h[(size_t)(b*H2 + min(oy0, H2-1)) * H2 * 8], p0c, p1c, q4);

    #pragma unroll
    for (int i = 0; i < 6; i++) {
        if (i < 5)
            load_ky1(nxt, &g_c2h[(size_t)(b*H2 + min(oy0+i+1, H2-1)) * H2 * 8],
                     p0c, p1c, q4);
        #pragma unroll
        for (int kx = 0; kx < 3; kx++) {
            uint32_t ah[4] = {cur[kx*4+0], cur[kx*4+1], cur[kx*4+2], cur[kx*4+3]};
            #pragma unroll
            for (int r = 0; r < 4; r++) {
                if (r > i || r < i - 2) continue;
                const int kc = 3*(i - r) + kx;
                uint2 f0 = sWf[(kc*4 + 0)*32 + lane];
                uint2 f1 = sWf[(kc*4 + 1)*32 + lane];
                uint2 f2 = sWf[(kc*4 + 2)*32 + lane];
                uint2 f3 = sWf[(kc*4 + 3)*32 + lane];
                mma16816h(acc[r][0], ah, f0.x, f0.y);
                mma16816h(acc[r][1], ah, f1.x, f1.y);
                mma16816h(acc[r][2], ah, f2.x, f2.y);
                mma16816h(acc[r][3], ah, f3.x, f3.y);
            }
        }
        #pragma unroll
        for (int j = 0; j < 12; j++) cur[j] = nxt[j];
    }

    #pragma unroll
    for (int r = 0; r < 4; r++) {
        const int oy = oy0 + r;
        if (oy >= H3) break;
        const size_t rowbase = (size_t)oy * H3;
        #pragma unroll
        for (int px = 0; px < 2; px++) {
            const int pp = px ? p1 : p0;
            float o[6];
            #pragma unroll
            for (int k = 0; k < 6; k++) o[k] = 0.f;
            #pragma unroll
            for (int cg = 0; cg < 4; cg++) {
                #pragma unroll
                for (int j = 0; j < 2; j++) {
                    const int ch = cg*8 + ci0 + j;
                    float t = acc[r][cg][px*2 + j] + sBA[ch];
                    t = (t >= 0.f) ? t : sBA[32+ch]*t;
                    o[0] = fmaf(t, sHW[0][ch], o[0]);
                    o[1] = fmaf(t, sHW[1][ch], o[1]);
                    o[2] = fmaf(t, sHW[2][ch], o[2]);
                    o[3] = fmaf(t, sHW[3][ch], o[3]);
                    o[4] = fmaf(t, sHW[4][ch], o[4]);
                    o[5] = fmaf(t, sHW[5][ch], o[5]);
                }
            }
            #pragma unroll
            for (int off = 1; off <= 2; off <<= 1)
                #pragma unroll
                for (int k = 0; k < 6; k++)
                    o[k] += __shfl_xor_sync(0xffffffffu, o[k], off);

            float l0 = o[0] + sHB[0], l1 = o[1] + sHB[1];
            float m  = fmaxf(l0, l1);
            float e0 = expf(l0 - m), e1 = expf(l1 - m);
            float inv = 1.f / (e0 + e1);
            float pr0 = e0 * inv, pr1 = e1 * inv;

            if (pp < H3) {
                const size_t p = rowbase + pp;
                regp[(size_t)(b*4+q)*P3 + p] = o[2+q] + sHB[2+q];
                if (q == 0) probp[(size_t)(b*2+0)*P3 + p] = pr0;
                if (q == 1) probp[(size_t)(b*2+1)*P3 + p] = pr1;
            }
        }
    }
}

// ---------------------------------------------------------------------------
extern "C" void kernel_launch(void* const* d_in, const int* in_sizes, int n_in,
                              void* d_out, int out_size)
{
    const float* x    = (const float*)d_in[0];
    const float* c1w  = (const float*)d_in[1];
    const float* c1b  = (const float*)d_in[2];
    const float* p1a  = (const float*)d_in[3];
    const float* c2w  = (const float*)d_in[4];
    const float* c2b  = (const float*)d_in[5];
    const float* p2a  = (const float*)d_in[6];
    const float* c3w  = (const float*)d_in[7];
    const float* c3b  = (const float*)d_in[8];
    const float* p3a  = (const float*)d_in[9];
    const float* c41w = (const float*)d_in[10];
    const float* c41b = (const float*)d_in[11];
    const float* c42w = (const float*)d_in[12];
    const float* c42b = (const float*)d_in[13];
    float* out = (float*)d_out;

    {
        dim3 grd((HP + 63) / 64, HP, B);   // 6 x 359 x 16
        k_conv1_mma<<<grd, 256>>>(x, c1w, c1b, p1a);
    }
    {
        dim3 grd((H2 + 127) / 128, (H2 + 3) / 4, B);
        k_conv2_mma<<<grd, 256>>>(c2w, c2b, p2a);
    }
    {
        dim3 grd((H3 + 127) / 128, (H3 + 3) / 4, B);
        k_conv3_heads<<<grd, 256>>>(c3w, c3b, p3a, c41w, c41b, c42w, c42b, out);
    }
}

// round 16
// speedup vs baseline: 1.1670x; 1.1670x over previous
#include <cuda_runtime.h>
#include <cuda_fp16.h>
#include <math.h>
#include <stdint.h>

// ---------------------------------------------------------------------------
// MTCNN P-Net forward. fp16 tensor-core path with PAIRED activation layout:
// per pixel 8 u32, slot q4*2+{0,1} holds the {q4, q4+4} fragment pair ->
// consumers fetch one uint2 (LDG.64) per fragment pair (6 loads/input row).
// conv1: scalar FFMA2 (norm folded), div-free staging.
// conv2/conv3: mma.sync fp16 ROW-STREAMING; conv3 fuses heads + softmax.
// ---------------------------------------------------------------------------

#define B       16
#define H0      720
#define HP      359
#define H2      357
#define H3      355
#define P3      (H3*H3)

typedef unsigned long long ull;

__device__ __forceinline__ ull pack2(float a, float b) {
    ull r;
    asm("mov.b64 %0, {%1,%2};" : "=l"(r)
        : "r"(__float_as_uint(a)), "r"(__float_as_uint(b)));
    return r;
}
__device__ __forceinline__ void unpack2(ull v, float& a, float& b) {
    unsigned lo, hi;
    asm("mov.b64 {%0,%1}, %2;" : "=r"(lo), "=r"(hi) : "l"(v));
    a = __uint_as_float(lo); b = __uint_as_float(hi);
}
__device__ __forceinline__ void fma2(ull& d, ull a, ull b) {
    asm("fma.rn.f32x2 %0, %1, %2, %3;" : "=l"(d) : "l"(a), "l"(b), "l"(d));
}

// activations, PAIRED layout: pixel*8 + q4*2 + {0 = slot q4, 1 = slot q4+4}
__device__ uint32_t g_p1h[(size_t)B*HP*HP*8];
__device__ uint32_t g_c2h[(size_t)B*H2*H2*8];

// ======================= mma.sync helpers (fp16) ===========================
__device__ __forceinline__ void mma16816h(float* d, const uint32_t* a,
                                          uint32_t b0, uint32_t b1) {
    asm volatile(
        "mma.sync.aligned.m16n8k16.row.col.f32.f16.f16.f32 "
        "{%0,%1,%2,%3}, {%4,%5,%6,%7}, {%8,%9}, {%0,%1,%2,%3};"
        : "+f"(d[0]), "+f"(d[1]), "+f"(d[2]), "+f"(d[3])
        : "r"(a[0]), "r"(a[1]), "r"(a[2]), "r"(a[3]), "r"(b0), "r"(b1));
}

// load one input-row batch: 6 uint2 (kx 0..2 x {p0,p1}); .x = slot q4, .y = q4+4
__device__ __forceinline__ void load_ky1(uint2 (&L)[6], const uint32_t* rp,
                                         int p0c, int p1c, int q4) {
    #pragma unroll
    for (int kx = 0; kx < 3; kx++) {
        L[kx*2+0] = *(const uint2*)&rp[(p0c + kx)*8 + q4*2];
        L[kx*2+1] = *(const uint2*)&rp[(p1c + kx)*8 + q4*2];
    }
}

// ---------------------------------------------------------------------------
// Kernel 1: conv1(3x3,3->10) + PReLU + maxpool2 -> fp16 paired ch-last
// ---------------------------------------------------------------------------
__device__ __forceinline__ void conv1_taps(
    ull (&acc)[5][4], const ull sWp[5][3][9], int ci, int ky,
    const ull* top, const ull* bot)
{
    #pragma unroll
    for (int kx = 0; kx < 3; kx++) {
        #pragma unroll
        for (int cp = 0; cp < 5; cp++) {
            ull wp = sWp[cp][ci][ky*3+kx];
            fma2(acc[cp][0], wp, top[kx]);
            fma2(acc[cp][1], wp, top[kx+1]);
            fma2(acc[cp][2], wp, bot[kx]);
            fma2(acc[cp][3], wp, bot[kx+1]);
        }
    }
}

__global__ __launch_bounds__(128, 8) void k_conv1_pool(
    const float* __restrict__ x, const float* __restrict__ w1,
    const float* __restrict__ b1, const float* __restrict__ a1)
{
    __shared__ ull   sWp[5][3][9];
    __shared__ ull   sIn[3][10][66];
    __shared__ float sB[10], sA[10];

    const int b   = blockIdx.z;
    const int px0 = blockIdx.x * 32;
    const int py0 = blockIdx.y * 4;
    const int tid = threadIdx.y * 32 + threadIdx.x;
    const float SC = 0.0078125f;

    for (int i = tid; i < 135; i += 128) {
        int cp = i / 27, ci = (i % 27) / 9, k = i % 9;
        sWp[cp][ci][k] = pack2(w1[(2*cp)*27 + ci*9 + k] * SC,
                               w1[(2*cp+1)*27 + ci*9 + k] * SC);
    }
    if (tid < 10) {
        float s = 0.f;
        #pragma unroll
        for (int k = 0; k < 27; k++) s += w1[tid*27 + k];
        sB[tid] = b1[tid] - 127.5f * SC * s;
        sA[tid] = a1[tid];
    }

    const int row0 = 2*py0, col0 = 2*px0;
    {
        const int c  = tid & 63;
        const int r2 = tid >> 6;
        const int gc = col0 + c;
        const bool cok = (gc < H0);
        #pragma unroll
        for (int ci = 0; ci < 3; ci++) {
            #pragma unroll
            for (int r = 0; r < 5; r++) {
                const int rr = 2*r + r2;
                const int gr = row0 + rr;
                float v = 0.f;
                if (cok && gr < H0) v = x[((b*3+ci)*H0 + gr)*H0 + gc];
                sIn[ci][rr][c] = pack2(v, v);
            }
        }
        if (tid < 60) {
            int ci = tid / 20, rem = tid % 20;
            int rr = rem >> 1, c2 = 64 + (rem & 1);
            int gr = row0 + rr, gc2 = col0 + c2;
            float v = 0.f;
            if (gr < H0 && gc2 < H0) v = x[((b*3+ci)*H0 + gr)*H0 + gc2];
            sIn[ci][rr][c2] = pack2(v, v);
        }
    }
    __syncthreads();

    const int px = px0 + threadIdx.x;
    const int py = py0 + threadIdx.y;
    if (px >= HP || py >= HP) return;

    ull acc[5][4];
    #pragma unroll
    for (int cp = 0; cp < 5; cp++) {
        ull bb = pack2(sB[2*cp], sB[2*cp+1]);
        acc[cp][0]=bb; acc[cp][1]=bb; acc[cp][2]=bb; acc[cp][3]=bb;
    }

    const int lr = 2*threadIdx.y, lc = 2*threadIdx.x;
    #pragma unroll
    for (int ci = 0; ci < 3; ci++) {
        ull qa[4], qb[4];
        #pragma unroll
        for (int j = 0; j < 4; j++) qa[j] = sIn[ci][lr  ][lc+j];
        #pragma unroll
        for (int j = 0; j < 4; j++) qb[j] = sIn[ci][lr+1][lc+j];
        conv1_taps(acc, sWp, ci, 0, qa, qb);
        #pragma unroll
        for (int j = 0; j < 4; j++) qa[j] = sIn[ci][lr+2][lc+j];
        conv1_taps(acc, sWp, ci, 1, qb, qa);
        #pragma unroll
        for (int j = 0; j < 4; j++) qb[j] = sIn[ci][lr+3][lc+j];
        conv1_taps(acc, sWp, ci, 2, qa, qb);
    }

    float v[16];
    #pragma unroll
    for (int cp = 0; cp < 5; cp++) {
        float a0 = sA[2*cp], a1v = sA[2*cp+1];
        float m0 = -INFINITY, m1 = -INFINITY;
        #pragma unroll
        for (int k = 0; k < 4; k++) {
            float v0, v1; unpack2(acc[cp][k], v0, v1);
            v0 = (v0 >= 0.f) ? v0 : a0*v0;
            v1 = (v1 >= 0.f) ? v1 : a1v*v1;
            m0 = fmaxf(m0, v0); m1 = fmaxf(m1, v1);
        }
        v[2*cp] = m0; v[2*cp+1] = m1;
    }
    #pragma unroll
    for (int c = 10; c < 16; c++) v[c] = 0.f;

    // PAIRED store: slot q4*2 = half2(ch 2q4, 2q4+1); slot q4*2+1 = half2(2q4+8, 2q4+9)
    uint32_t h[8];
    #pragma unroll
    for (int q4 = 0; q4 < 4; q4++) {
        __half2 lo = __floats2half2_rn(v[2*q4],     v[2*q4+1]);
        __half2 hi = __floats2half2_rn(v[2*q4 + 8], v[2*q4+9]);
        h[q4*2]   = *(uint32_t*)&lo;
        h[q4*2+1] = *(uint32_t*)&hi;
    }

    uint4* dst = (uint4*)&g_p1h[((size_t)(b*HP + py)*HP + px)*8];
    dst[0] = make_uint4(h[0], h[1], h[2], h[3]);
    dst[1] = make_uint4(h[4], h[5], h[6], h[7]);
}

// ---------------------------------------------------------------------------
// Kernel 2: conv2 via mma.sync fp16, ROW-STREAMING, paired loads.
// ---------------------------------------------------------------------------
__global__ __launch_bounds__(256, 2) void k_conv2_mma(
    const float* __restrict__ w, const float* __restrict__ bias,
    const float* __restrict__ alpha)
{
    __shared__ uint2 sWf[9*2*32];
    __shared__ float sBA[32];

    const int b    = blockIdx.z;
    const int ox0  = blockIdx.x * 128;
    const int oy0  = blockIdx.y * 4;
    const int tid  = threadIdx.x;
    const int wid  = tid >> 5;
    const int lane = tid & 31;

    for (int f = tid; f < 9*2*32; f += 256) {
        int kc = f >> 6, cg = (f >> 5) & 1, ln = f & 31;
        int g = ln >> 2, ci0 = (ln & 3) * 2;
        int co = cg*8 + g;
        int ky = kc / 3, kx = kc % 3;
        float w0 = (ci0   < 10) ? w[((co*10 + ci0  )*3 + ky)*3 + kx] : 0.f;
        float w1v= (ci0+1 < 10) ? w[((co*10 + ci0+1)*3 + ky)*3 + kx] : 0.f;
        float w2 = (ci0+8 < 10) ? w[((co*10 + ci0+8)*3 + ky)*3 + kx] : 0.f;
        float w3 = (ci0+9 < 10) ? w[((co*10 + ci0+9)*3 + ky)*3 + kx] : 0.f;
        __half2 b0 = __floats2half2_rn(w0, w1v);
        __half2 b1 = __floats2half2_rn(w2, w3);
        sWf[f] = make_uint2(*(uint32_t*)&b0, *(uint32_t*)&b1);
    }
    if (tid < 16) { sBA[tid] = bias[tid]; sBA[16+tid] = alpha[tid]; }
    __syncthreads();

    const int q4  = lane & 3;
    const int g   = lane >> 2;
    const int ci0 = q4 * 2;

    const int p0  = ox0 + wid * 16 + g;
    const int p1  = p0 + 8;
    const int p0c = min(p0, H2 - 1);
    const int p1c = min(p1, H2 - 1);

    float acc[4][2][4];
    #pragma unroll
    for (int r = 0; r < 4; r++)
        #pragma unroll
        for (int cg = 0; cg < 2; cg++)
            #pragma unroll
            for (int j = 0; j < 4; j++) acc[r][cg][j] = 0.f;

    uint2 cur[6], nxt[6];
    load_ky1(cur, &g_p1h[(size_t)(b*HP + min(oy0, HP-1)) * HP * 8], p0c, p1c, q4);

    #pragma unroll
    for (int i = 0; i < 6; i++) {
        if (i < 5)
            load_ky1(nxt, &g_p1h[(size_t)(b*HP + min(oy0+i+1, HP-1)) * HP * 8],
                     p0c, p1c, q4);
        #pragma unroll
        for (int kx = 0; kx < 3; kx++) {
            uint32_t ah[4] = {cur[kx*2+0].x, cur[kx*2+1].x,
                              cur[kx*2+0].y, cur[kx*2+1].y};
            #pragma unroll
            for (int r = 0; r < 4; r++) {
                if (r > i || r < i - 2) continue;
                const int kc = 3*(i - r) + kx;
                uint2 f0 = sWf[(kc*2 + 0)*32 + lane];
                uint2 f1 = sWf[(kc*2 + 1)*32 + lane];
                mma16816h(acc[r][0], ah, f0.x, f0.y);
                mma16816h(acc[r][1], ah, f1.x, f1.y);
            }
        }
        #pragma unroll
        for (int j = 0; j < 6; j++) cur[j] = nxt[j];
    }

    #pragma unroll
    for (int r = 0; r < 4; r++) {
        const int oy = oy0 + r;
        if (oy >= H2) break;
        const size_t rowbase = (size_t)(b*H2 + oy) * H2;
        #pragma unroll
        for (int cg = 0; cg < 2; cg++) {
            const int co = cg*8 + ci0;
            const float b0 = sBA[co], b1 = sBA[co+1];
            const float a0 = sBA[16+co], a1 = sBA[16+co+1];
            float t0 = acc[r][cg][0] + b0, t1 = acc[r][cg][1] + b1;
            float t2 = acc[r][cg][2] + b0, t3 = acc[r][cg][3] + b1;
            float o00 = (t0 >= 0.f) ? t0 : a0*t0;
            float o01 = (t1 >= 0.f) ? t1 : a1*t1;
            float o10 = (t2 >= 0.f) ? t2 : a0*t2;
            float o11 = (t3 >= 0.f) ? t3 : a1*t3;
            __half2 s0 = __floats2half2_rn(o00, o01);
            __half2 s1 = __floats2half2_rn(o10, o11);
            // PAIRED store: slot index = q4*2 + cg  (cg=0 -> slot q4, cg=1 -> q4+4)
            if (p0 < H2) g_c2h[(rowbase + p0)*8 + q4*2 + cg] = *(uint32_t*)&s0;
            if (p1 < H2) g_c2h[(rowbase + p1)*8 + q4*2 + cg] = *(uint32_t*)&s1;
        }
    }
}

// ---------------------------------------------------------------------------
// Kernel 3: conv3 ROW-STREAMING + fused heads + softmax, paired loads.
// ---------------------------------------------------------------------------
__global__ __launch_bounds__(256, 2) void k_conv3_heads(
    const float* __restrict__ w, const float* __restrict__ bias,
    const float* __restrict__ alpha,
    const float* __restrict__ w41, const float* __restrict__ b41,
    const float* __restrict__ w42, const float* __restrict__ b42,
    float* __restrict__ out)
{
    __shared__ uint2 sWf[9*4*32];
    __shared__ float sBA[64];
    __shared__ float sHW[6][32];
    __shared__ float sHB[6];

    const int b    = blockIdx.z;
    const int ox0  = blockIdx.x * 128;
    const int oy0  = blockIdx.y * 4;
    const int tid  = threadIdx.x;
    const int wid  = tid >> 5;
    const int lane = tid & 31;

    for (int f = tid; f < 9*4*32; f += 256) {
        int kc = f >> 7, cg = (f >> 5) & 3, ln = f & 31;
        int g = ln >> 2, ci0 = (ln & 3) * 2;
        int co = cg*8 + g;
        int ky = kc / 3, kx = kc % 3;
        __half2 b0 = __floats2half2_rn(w[((co*16 + ci0  )*3 + ky)*3 + kx],
                                       w[((co*16 + ci0+1)*3 + ky)*3 + kx]);
        __half2 b1 = __floats2half2_rn(w[((co*16 + ci0+8)*3 + ky)*3 + kx],
                                       w[((co*16 + ci0+9)*3 + ky)*3 + kx]);
        sWf[f] = make_uint2(*(uint32_t*)&b0, *(uint32_t*)&b1);
    }
    if (tid < 32) { sBA[tid] = bias[tid]; sBA[32+tid] = alpha[tid]; }
    if (tid < 64)  sHW[tid/32][tid%32] = w41[tid];
    if (tid >= 64 && tid < 192) sHW[2 + (tid-64)/32][(tid-64)%32] = w42[tid-64];
    if (tid < 2) sHB[tid] = b41[tid];
    if (tid >= 2 && tid < 6) sHB[tid] = b42[tid-2];
    __syncthreads();

    const int q4  = lane & 3;
    const int g   = lane >> 2;
    const int ci0 = q4 * 2;
    const int q   = q4;

    const int p0  = ox0 + wid * 16 + g;
    const int p1  = p0 + 8;
    const int p0c = min(p0, H3 - 1);
    const int p1c = min(p1, H3 - 1);

    float* regp  = out;
    float* probp = out + (size_t)B * 4 * P3;

    float acc[4][4][4];
    #pragma unroll
    for (int r = 0; r < 4; r++)
        #pragma unroll
        for (int cg = 0; cg < 4; cg++)
            #pragma unroll
            for (int j = 0; j < 4; j++) acc[r][cg][j] = 0.f;

    uint2 cur[6], nxt[6];
    load_ky1(cur, &g_c2h[(size_t)(b*H2 + min(oy0, H2-1)) * H2 * 8], p0c, p1c, q4);

    #pragma unroll
    for (int i = 0; i < 6; i++) {
        if (i < 5)
            load_ky1(nxt, &g_c2h[(size_t)(b*H2 + min(oy0+i+1, H2-1)) * H2 * 8],
                     p0c, p1c, q4);
        #pragma unroll
        for (int kx = 0; kx < 3; kx++) {
            uint32_t ah[4] = {cur[kx*2+0].x, cur[kx*2+1].x,
                              cur[kx*2+0].y, cur[kx*2+1].y};
            #pragma unroll
            for (int r = 0; r < 4; r++) {
                if (r > i || r < i - 2) continue;
                const int kc = 3*(i - r) + kx;
                uint2 f0 = sWf[(kc*4 + 0)*32 + lane];
                uint2 f1 = sWf[(kc*4 + 1)*32 + lane];
                uint2 f2 = sWf[(kc*4 + 2)*32 + lane];
                uint2 f3 = sWf[(kc*4 + 3)*32 + lane];
                mma16816h(acc[r][0], ah, f0.x, f0.y);
                mma16816h(acc[r][1], ah, f1.x, f1.y);
                mma16816h(acc[r][2], ah, f2.x, f2.y);
                mma16816h(acc[r][3], ah, f3.x, f3.y);
            }
        }
        #pragma unroll
        for (int j = 0; j < 6; j++) cur[j] = nxt[j];
    }

    #pragma unroll
    for (int r = 0; r < 4; r++) {
        const int oy = oy0 + r;
        if (oy >= H3) break;
        const size_t rowbase = (size_t)oy * H3;
        #pragma unroll
        for (int px = 0; px < 2; px++) {
            const int pp = px ? p1 : p0;
            float o[6];
            #pragma unroll
            for (int k = 0; k < 6; k++) o[k] = 0.f;
            #pragma unroll
            for (int cg = 0; cg < 4; cg++) {
                #pragma unroll
                for (int j = 0; j < 2; j++) {
                    const int ch = cg*8 + ci0 + j;
                    float t = acc[r][cg][px*2 + j] + sBA[ch];
                    t = (t >= 0.f) ? t : sBA[32+ch]*t;
                    o[0] = fmaf(t, sHW[0][ch], o[0]);
                    o[1] = fmaf(t, sHW[1][ch], o[1]);
                    o[2] = fmaf(t, sHW[2][ch], o[2]);
                    o[3] = fmaf(t, sHW[3][ch], o[3]);
                    o[4] = fmaf(t, sHW[4][ch], o[4]);
                    o[5] = fmaf(t, sHW[5][ch], o[5]);
                }
            }
            #pragma unroll
            for (int off = 1; off <= 2; off <<= 1)
                #pragma unroll
                for (int k = 0; k < 6; k++)
                    o[k] += __shfl_xor_sync(0xffffffffu, o[k], off);

            float l0 = o[0] + sHB[0], l1 = o[1] + sHB[1];
            float m  = fmaxf(l0, l1);
            float e0 = expf(l0 - m), e1 = expf(l1 - m);
            float inv = 1.f / (e0 + e1);
            float pr0 = e0 * inv, pr1 = e1 * inv;

            if (pp < H3) {
                const size_t p = rowbase + pp;
                regp[(size_t)(b*4+q)*P3 + p] = o[2+q] + sHB[2+q];
                if (q == 0) probp[(size_t)(b*2+0)*P3 + p] = pr0;
                if (q == 1) probp[(size_t)(b*2+1)*P3 + p] = pr1;
            }
        }
    }
}

// ---------------------------------------------------------------------------
extern "C" void kernel_launch(void* const* d_in, const int* in_sizes, int n_in,
                              void* d_out, int out_size)
{
    const float* x    = (const float*)d_in[0];
    const float* c1w  = (const float*)d_in[1];
    const float* c1b  = (const float*)d_in[2];
    const float* p1a  = (const float*)d_in[3];
    const float* c2w  = (const float*)d_in[4];
    const float* c2b  = (const float*)d_in[5];
    const float* p2a  = (const float*)d_in[6];
    const float* c3w  = (const float*)d_in[7];
    const float* c3b  = (const float*)d_in[8];
    const float* p3a  = (const float*)d_in[9];
    const float* c41w = (const float*)d_in[10];
    const float* c41b = (const float*)d_in[11];
    const float* c42w = (const float*)d_in[12];
    const float* c42b = (const float*)d_in[13];
    float* out = (float*)d_out;

    {
        dim3 blk(32, 4);
        dim3 grd((HP + 31) / 32, (HP + 3) / 4, B);
        k_conv1_pool<<<grd, blk>>>(x, c1w, c1b, p1a);
    }
    {
        dim3 grd((H2 + 127) / 128, (H2 + 3) / 4, B);
        k_conv2_mma<<<grd, 256>>>(c2w, c2b, p2a);
    }
    {
        dim3 grd((H3 + 127) / 128, (H3 + 3) / 4, B);
        k_conv3_heads<<<grd, 256>>>(c3w, c3b, p3a, c41w, c41b, c42w, c42b, out);
    }
}